// round 15
// baseline (speedup 1.0000x reference)
#include <cuda_runtime.h>
#include <cuda_bf16.h>
#include <cstdint>

#define BB 128          // graphs
#define NN 68           // landmarks per graph
#define CC 3            // input channels
#define PP 32           // patch
#define KK 16           // conv kernels
#define FD 64           // feature dim
#define GH 128          // gcn hidden
#define OUTD 2
#define EG (8*NN)       // 544 edges per graph
#define TT (BB*NN)      // 8704 nodes
#define FLAT (KK*(PP/2)*(PP/2))   // 4096
#define KSPLIT 4
#define NCHUNK ((FLAT / KSPLIT) / 64)   // 16

// ---- scratch (allocation-free: device globals) ----
__device__ float g_flat[(size_t)TT * FLAT];               // fp32 activations
__device__ float g_part[KSPLIT][(size_t)BB * NN * FD];    // k-split partials
__device__ float g_xw[(size_t)TT * GH];

__device__ __forceinline__ uint32_t bf2(float lo, float hi) {
    uint32_t r; asm("cvt.rn.bf16x2.f32 %0, %1, %2;" : "=r"(r) : "f"(hi), "f"(lo)); return r;
}

// ============================================================
// Shared MMA helpers
// ============================================================
#define SWB(row, byteoff) (((row) * 128) + ((byteoff) ^ (((row) & 7) << 4)))

__device__ __forceinline__ uint32_t smem_u32(const void* p) {
    uint32_t a;
    asm("{ .reg .u64 t; cvta.to.shared.u64 t, %1; cvt.u32.u64 %0, t; }" : "=r"(a) : "l"(p));
    return a;
}
__device__ __forceinline__ void ldsm_x4(uint32_t& r0, uint32_t& r1, uint32_t& r2, uint32_t& r3, uint32_t a) {
    asm volatile("ldmatrix.sync.aligned.m8n8.x4.shared.b16 {%0,%1,%2,%3}, [%4];"
                 : "=r"(r0), "=r"(r1), "=r"(r2), "=r"(r3) : "r"(a));
}
__device__ __forceinline__ void ldsm_x2(uint32_t& r0, uint32_t& r1, uint32_t a) {
    asm volatile("ldmatrix.sync.aligned.m8n8.x2.shared.b16 {%0,%1}, [%2];"
                 : "=r"(r0), "=r"(r1) : "r"(a));
}
#define MMA16816(c, a0, a1, a2, a3, b0, b1) \
    asm volatile("mma.sync.aligned.m16n8k16.row.col.f32.bf16.bf16.f32 " \
        "{%0,%1,%2,%3}, {%4,%5,%6,%7}, {%8,%9}, {%0,%1,%2,%3};" \
        : "+f"((c)[0]), "+f"((c)[1]), "+f"((c)[2]), "+f"((c)[3]) \
        : "r"(a0), "r"(a1), "r"(a2), "r"(a3), "r"(b0), "r"(b1))

// ============================================================
// Stage 1: direct conv3x3 (SAME) as implicit GEMM on MMA,
// + bias + relu + maxpool2x2 fused epilogue.
// block = one node. A = im2col [128 px x 32], B = W [16 x 32].
// 8 M-iterations cover 1024 pre-pool pixels.
// ============================================================
#define CV_XS 0                    // 12288: x patch fp32
#define CV_BH 12288                // 2048
#define CV_BL 14336                // 2048
#define CV_AH 16384                // 16384
#define CV_AL 32768                // 16384
#define CV_YS 49152                // 128*17*4 = 8704
#define CV_TOTAL 57856
#define YP 17                      // Ys pitch (floats)

template<int BASE>
__device__ __forceinline__ void build_taps(const float (*xs)[PP][PP], int y, int x, float* vals)
{
    #pragma unroll
    for (int i = 0; i < 16; i++) {
        const int kidx = BASE + i;
        float v = 0.f;
        if (kidx < 27) {
            const int c  = kidx / 9;
            const int rr = kidx % 9;
            const int dy = rr / 3;
            const int dx = rr % 3;
            int yy = y + dy - 1, xx = x + dx - 1;
            if (yy >= 0 && yy < PP && xx >= 0 && xx < PP) v = xs[c][yy][xx];
        }
        vals[i] = v;
    }
}

__global__ __launch_bounds__(256) void conv_pool_kernel(
    const float* __restrict__ x,
    const float* __restrict__ conv_w,
    const float* __restrict__ conv_b)
{
    extern __shared__ char sm[];
    uint32_t smb = smem_u32(sm);
    float (*xs)[PP][PP] = (float (*)[PP][PP])(sm + CV_XS);
    float* Ys = (float*)(sm + CV_YS);
    __shared__ float bsh[KK];

    int t = blockIdx.x;
    int n = t % NN;
    int tid = threadIdx.x;
    int wid = tid >> 5;
    int lane = tid & 31;

    // load x patch (3072 floats = 768 float4)
    const float4* xp4 = (const float4*)(x + (size_t)t * (CC * PP * PP));
    #pragma unroll
    for (int i = 0; i < 3; i++)
        ((float4*)(sm + CV_XS))[tid + i * 256] = xp4[tid + i * 256];
    if (tid < KK) bsh[tid] = conv_b[n * KK + tid];

    // B: W[k][kidx], kidx 27..31 zero, split hi/lo, swizzled
    if (tid < 32) {
        int k = tid >> 1, khalf = tid & 1;
        float wv[16];
        #pragma unroll
        for (int i = 0; i < 16; i++) {
            int kidx = khalf * 16 + i;
            wv[i] = (kidx < 27) ? conv_w[((size_t)n * KK + k) * 27 + kidx] : 0.f;
        }
        #pragma unroll
        for (int j = 0; j < 4; j++) {
            uint32_t h0 = bf2(wv[4*j], wv[4*j+1]);
            uint32_t h1 = bf2(wv[4*j+2], wv[4*j+3]);
            float h0x = __bfloat162float(__ushort_as_bfloat16((unsigned short)(h0 & 0xFFFF)));
            float h0y = __bfloat162float(__ushort_as_bfloat16((unsigned short)(h0 >> 16)));
            float h1x = __bfloat162float(__ushort_as_bfloat16((unsigned short)(h1 & 0xFFFF)));
            float h1y = __bfloat162float(__ushort_as_bfloat16((unsigned short)(h1 >> 16)));
            uint32_t l0 = bf2(wv[4*j] - h0x, wv[4*j+1] - h0y);
            uint32_t l1 = bf2(wv[4*j+2] - h1x, wv[4*j+3] - h1y);
            uint32_t d = SWB(k, khalf * 32 + j * 8);
            *(uint2*)(sm + CV_BH + d) = make_uint2(h0, h1);
            *(uint2*)(sm + CV_BL + d) = make_uint2(l0, l1);
        }
    }
    __syncthreads();

    // preload B fragments (reused across all 8 iterations)
    int brow = lane & 7;
    int bcolb = ((lane >> 3) & 1) * 16;
    uint32_t bfh[2][2][2], bfl[2][2][2];   // [nt][ks][reg]
    #pragma unroll
    for (int nt = 0; nt < 2; nt++)
        #pragma unroll
        for (int ks = 0; ks < 2; ks++) {
            uint32_t bd = SWB(nt * 8 + brow, ks * 32 + bcolb);
            ldsm_x2(bfh[nt][ks][0], bfh[nt][ks][1], smb + CV_BH + bd);
            ldsm_x2(bfl[nt][ks][0], bfl[nt][ks][1], smb + CV_BL + bd);
        }

    int m_row = tid & 127;          // A row within tile
    int khalf = tid >> 7;           // 0: kidx 0-15, 1: kidx 16-31 (warp-uniform)
    int arow = lane & 15;
    int acolb = (lane >> 4) * 16;
    int r0 = lane >> 2, c0_ = (lane & 3) * 2;

    float* outp = &g_flat[(size_t)t * FLAT];

    #pragma unroll 1
    for (int iter = 0; iter < 8; iter++) {
        // ---- build A tile: 128 px x 32 kidx, hi/lo split ----
        {
            int yl = m_row >> 5;                // 0..3
            int xc = m_row & 31;
            int yg = iter * 4 + yl;
            float vals[16];
            if (khalf == 0) build_taps<0>(xs, yg, xc, vals);
            else            build_taps<16>(xs, yg, xc, vals);
            #pragma unroll
            for (int j = 0; j < 4; j++) {
                uint32_t h0 = bf2(vals[4*j], vals[4*j+1]);
                uint32_t h1 = bf2(vals[4*j+2], vals[4*j+3]);
                float h0x = __bfloat162float(__ushort_as_bfloat16((unsigned short)(h0 & 0xFFFF)));
                float h0y = __bfloat162float(__ushort_as_bfloat16((unsigned short)(h0 >> 16)));
                float h1x = __bfloat162float(__ushort_as_bfloat16((unsigned short)(h1 & 0xFFFF)));
                float h1y = __bfloat162float(__ushort_as_bfloat16((unsigned short)(h1 >> 16)));
                uint32_t l0 = bf2(vals[4*j] - h0x, vals[4*j+1] - h0y);
                uint32_t l1 = bf2(vals[4*j+2] - h1x, vals[4*j+3] - h1y);
                uint32_t d = SWB(m_row, khalf * 32 + j * 8);
                *(uint2*)(sm + CV_AH + d) = make_uint2(h0, h1);
                *(uint2*)(sm + CV_AL + d) = make_uint2(l0, l1);
            }
        }
        __syncthreads();   // A ready; prev pool done reading Ys

        // ---- MMA: warp w handles m-tile w ----
        {
            float acc[2][4];
            #pragma unroll
            for (int nt = 0; nt < 2; nt++)
                #pragma unroll
                for (int q = 0; q < 4; q++) acc[nt][q] = 0.f;

            uint32_t ah[2][4], al[2][4];
            #pragma unroll
            for (int ks = 0; ks < 2; ks++) {
                uint32_t ad = SWB(wid * 16 + arow, ks * 32 + acolb);
                ldsm_x4(ah[ks][0], ah[ks][1], ah[ks][2], ah[ks][3], smb + CV_AH + ad);
                ldsm_x4(al[ks][0], al[ks][1], al[ks][2], al[ks][3], smb + CV_AL + ad);
            }
            #pragma unroll
            for (int ks = 0; ks < 2; ks++)
                #pragma unroll
                for (int nt = 0; nt < 2; nt++) {
                    MMA16816(acc[nt], ah[ks][0], ah[ks][1], ah[ks][2], ah[ks][3],
                             bfh[nt][ks][0], bfh[nt][ks][1]);          // hh
                    MMA16816(acc[nt], ah[ks][0], ah[ks][1], ah[ks][2], ah[ks][3],
                             bfl[nt][ks][0], bfl[nt][ks][1]);          // hl
                    MMA16816(acc[nt], al[ks][0], al[ks][1], al[ks][2], al[ks][3],
                             bfh[nt][ks][0], bfh[nt][ks][1]);          // lh
                }

            // D -> Ys
            int wr0 = wid * 16 + r0;
            #pragma unroll
            for (int nt = 0; nt < 2; nt++) {
                Ys[wr0 * YP + nt * 8 + c0_]       = acc[nt][0];
                Ys[wr0 * YP + nt * 8 + c0_ + 1]   = acc[nt][1];
                Ys[(wr0 + 8) * YP + nt * 8 + c0_]     = acc[nt][2];
                Ys[(wr0 + 8) * YP + nt * 8 + c0_ + 1] = acc[nt][3];
            }
        }
        __syncthreads();   // Ys ready

        // ---- pool 2x2 + bias + relu -> g_flat ----
        #pragma unroll
        for (int j = 0; j < 2; j++) {
            int o = tid + j * 256;          // 0..511
            int pcol = o & 15;
            int k    = (o >> 4) & 15;
            int pyl  = o >> 8;              // 0/1
            int mA = (2 * pyl) * 32 + 2 * pcol;
            float vA = Ys[mA * YP + k];
            float vB = Ys[(mA + 1) * YP + k];
            float vC = Ys[(mA + 32) * YP + k];
            float vD = Ys[(mA + 33) * YP + k];
            float v = fmaxf(fmaxf(vA, vB), fmaxf(vC, vD));
            outp[k * 256 + (iter * 2 + pyl) * 16 + pcol] = fmaxf(v + bsh[k], 0.f);
        }
        // next iteration's A-build may proceed; Ys protected by next syncthreads
    }
}

// ============================================================
// Stage 2: lin1 via mma.sync bf16 + ldmatrix (3-pass split)
// with register-prefetch software pipeline over K chunks
// ============================================================
#define L1_AH 0
#define L1_AL 16384
#define L1_BH 32768
#define L1_BL 40960
#define L1_TOTAL 49152

__global__ __launch_bounds__(256) void lin1_mma_kernel(const float* __restrict__ lin1_w)
{
    extern __shared__ char sm[];
    uint32_t smb = smem_u32(sm);

    int n  = blockIdx.x;
    int kh = blockIdx.y;
    int fbase = kh * (FLAT / KSPLIT);

    int tid  = threadIdx.x;
    int wid  = tid >> 5;
    int lane = tid & 31;
    int wm   = (wid & 3) * 32;
    int wn   = (wid >> 2) * 32;

    float acc[2][4][4];
    #pragma unroll
    for (int mt = 0; mt < 2; mt++)
        #pragma unroll
        for (int nt = 0; nt < 4; nt++)
            #pragma unroll
            for (int q = 0; q < 4; q++) acc[mt][nt][q] = 0.f;

    int arow = lane & 15;
    int acolb = (lane >> 4) * 16;
    int brow = lane & 7;
    int bcolb = ((lane >> 3) & 1) * 16;

    int bo = tid & 63;
    int bfs = (tid >> 6) * 16;

    float4 pa[8];
    float  pb[16];

    {
        int fc = fbase;
        #pragma unroll
        for (int j = 0; j < 8; j++) {
            int e = tid + j * 256;
            int row = e >> 4, q = e & 15;
            pa[j] = ((const float4*)g_flat)[(((size_t)(row * NN + n) * FLAT + fc) >> 2) + q];
        }
        const float* wsrc = lin1_w + ((size_t)n * FLAT + fc + bfs) * FD + bo;
        #pragma unroll
        for (int i = 0; i < 16; i++) pb[i] = wsrc[i * FD];
    }

    #pragma unroll 1
    for (int ci = 0; ci < NCHUNK; ci++) {
        __syncthreads();
        #pragma unroll
        for (int j = 0; j < 8; j++) {
            int e = tid + j * 256;
            int row = e >> 4, q = e & 15;
            float4 v = pa[j];
            uint32_t h0 = bf2(v.x, v.y), h1 = bf2(v.z, v.w);
            float hx = __bfloat162float(__ushort_as_bfloat16((unsigned short)(h0 & 0xFFFF)));
            float hy = __bfloat162float(__ushort_as_bfloat16((unsigned short)(h0 >> 16)));
            float hz = __bfloat162float(__ushort_as_bfloat16((unsigned short)(h1 & 0xFFFF)));
            float hw = __bfloat162float(__ushort_as_bfloat16((unsigned short)(h1 >> 16)));
            uint32_t l0 = bf2(v.x - hx, v.y - hy), l1 = bf2(v.z - hz, v.w - hw);
            uint32_t d = SWB(row, q * 8);
            *(uint2*)(sm + L1_AH + d) = make_uint2(h0, h1);
            *(uint2*)(sm + L1_AL + d) = make_uint2(l0, l1);
        }
        #pragma unroll
        for (int j = 0; j < 4; j++) {
            uint32_t h0 = bf2(pb[4*j], pb[4*j+1]);
            uint32_t h1 = bf2(pb[4*j+2], pb[4*j+3]);
            float h0x = __bfloat162float(__ushort_as_bfloat16((unsigned short)(h0 & 0xFFFF)));
            float h0y = __bfloat162float(__ushort_as_bfloat16((unsigned short)(h0 >> 16)));
            float h1x = __bfloat162float(__ushort_as_bfloat16((unsigned short)(h1 & 0xFFFF)));
            float h1y = __bfloat162float(__ushort_as_bfloat16((unsigned short)(h1 >> 16)));
            uint32_t l0 = bf2(pb[4*j] - h0x, pb[4*j+1] - h0y);
            uint32_t l1 = bf2(pb[4*j+2] - h1x, pb[4*j+3] - h1y);
            uint32_t d = SWB(bo, (bfs + 4*j) * 2);
            *(uint2*)(sm + L1_BH + d) = make_uint2(h0, h1);
            *(uint2*)(sm + L1_BL + d) = make_uint2(l0, l1);
        }
        if (ci + 1 < NCHUNK) {
            int fc = fbase + (ci + 1) * 64;
            #pragma unroll
            for (int j = 0; j < 8; j++) {
                int e = tid + j * 256;
                int row = e >> 4, q = e & 15;
                pa[j] = ((const float4*)g_flat)[(((size_t)(row * NN + n) * FLAT + fc) >> 2) + q];
            }
            const float* wsrc = lin1_w + ((size_t)n * FLAT + fc + bfs) * FD + bo;
            #pragma unroll
            for (int i = 0; i < 16; i++) pb[i] = wsrc[i * FD];
        }
        __syncthreads();

        #pragma unroll
        for (int ks = 0; ks < 4; ks++) {
            int kb = ks * 32;
            uint32_t ah[2][4], al[2][4];
            #pragma unroll
            for (int mt = 0; mt < 2; mt++) {
                int row = wm + mt * 16 + arow;
                uint32_t ad = SWB(row, kb + acolb);
                ldsm_x4(ah[mt][0], ah[mt][1], ah[mt][2], ah[mt][3], smb + L1_AH + ad);
                ldsm_x4(al[mt][0], al[mt][1], al[mt][2], al[mt][3], smb + L1_AL + ad);
            }
            uint32_t bh[4][2], bl[4][2];
            #pragma unroll
            for (int nt = 0; nt < 4; nt++) {
                int row = wn + nt * 8 + brow;
                uint32_t bd = SWB(row, kb + bcolb);
                ldsm_x2(bh[nt][0], bh[nt][1], smb + L1_BH + bd);
                ldsm_x2(bl[nt][0], bl[nt][1], smb + L1_BL + bd);
            }
            #pragma unroll
            for (int mt = 0; mt < 2; mt++)
                #pragma unroll
                for (int nt = 0; nt < 4; nt++) {
                    MMA16816(acc[mt][nt], ah[mt][0], ah[mt][1], ah[mt][2], ah[mt][3],
                             bh[nt][0], bh[nt][1]);
                    MMA16816(acc[mt][nt], ah[mt][0], ah[mt][1], ah[mt][2], ah[mt][3],
                             bl[nt][0], bl[nt][1]);
                    MMA16816(acc[mt][nt], al[mt][0], al[mt][1], al[mt][2], al[mt][3],
                             bh[nt][0], bh[nt][1]);
                }
        }
    }

    float* P = g_part[kh];
    int r0 = lane >> 2, c0 = (lane & 3) * 2;
    #pragma unroll
    for (int mt = 0; mt < 2; mt++) {
        int g0 = wm + mt * 16 + r0;
        #pragma unroll
        for (int nt = 0; nt < 4; nt++) {
            int o = wn + nt * 8 + c0;
            float* p0 = &P[(size_t)(g0 * NN + n) * FD + o];
            float* p1 = &P[(size_t)((g0 + 8) * NN + n) * FD + o];
            p0[0] = acc[mt][nt][0]; p0[1] = acc[mt][nt][1];
            p1[0] = acc[mt][nt][2]; p1[1] = acc[mt][nt][3];
        }
    }
}

// ============================================================
// Stage 3: xw = relu(sum parts + bias) @ gcn_w, via MMA.
// ============================================================
#define XW_AH 0
#define XW_AL 8192
#define XW_BH 16384
#define XW_BL 32768
#define XW_TOTAL 49152

__global__ __launch_bounds__(256) void gcn_xw_kernel(
    const float* __restrict__ lin1_b, const float* __restrict__ gcn_w)
{
    extern __shared__ char sm[];
    uint32_t smb = smem_u32(sm);
    int t0 = blockIdx.x * 64;
    int tid = threadIdx.x;
    int wid = tid >> 5;
    int lane = tid & 31;

    #pragma unroll
    for (int j = 0; j < 4; j++) {
        int e = tid + j * 256;
        int row = e >> 4, q = e & 15;
        int t = t0 + row, n = t % NN;
        size_t ix4 = (size_t)t * 16 + q;
        float sx = 0.f, sy = 0.f, sz = 0.f, sw = 0.f;
        #pragma unroll
        for (int p = 0; p < KSPLIT; p++) {
            float4 pv = ((const float4*)g_part[p])[ix4];
            sx += pv.x; sy += pv.y; sz += pv.z; sw += pv.w;
        }
        float4 lb = ((const float4*)lin1_b)[n * 16 + q];
        float vx = fmaxf(sx + lb.x, 0.f);
        float vy = fmaxf(sy + lb.y, 0.f);
        float vz = fmaxf(sz + lb.z, 0.f);
        float vw = fmaxf(sw + lb.w, 0.f);
        uint32_t h0 = bf2(vx, vy), h1 = bf2(vz, vw);
        float hx = __bfloat162float(__ushort_as_bfloat16((unsigned short)(h0 & 0xFFFF)));
        float hy = __bfloat162float(__ushort_as_bfloat16((unsigned short)(h0 >> 16)));
        float hz = __bfloat162float(__ushort_as_bfloat16((unsigned short)(h1 & 0xFFFF)));
        float hw = __bfloat162float(__ushort_as_bfloat16((unsigned short)(h1 >> 16)));
        uint32_t l0 = bf2(vx - hx, vy - hy), l1 = bf2(vz - hz, vw - hw);
        uint32_t d = SWB(row, q * 8);
        *(uint2*)(sm + XW_AH + d) = make_uint2(h0, h1);
        *(uint2*)(sm + XW_AL + d) = make_uint2(l0, l1);
    }
    {
        int o = tid & 127;
        int ks0 = (tid >> 7) * 32;
        float wv[32];
        #pragma unroll
        for (int i = 0; i < 32; i++) wv[i] = gcn_w[(ks0 + i) * GH + o];
        #pragma unroll
        for (int j = 0; j < 8; j++) {
            uint32_t h0 = bf2(wv[4*j], wv[4*j+1]);
            uint32_t h1 = bf2(wv[4*j+2], wv[4*j+3]);
            float h0x = __bfloat162float(__ushort_as_bfloat16((unsigned short)(h0 & 0xFFFF)));
            float h0y = __bfloat162float(__ushort_as_bfloat16((unsigned short)(h0 >> 16)));
            float h1x = __bfloat162float(__ushort_as_bfloat16((unsigned short)(h1 & 0xFFFF)));
            float h1y = __bfloat162float(__ushort_as_bfloat16((unsigned short)(h1 >> 16)));
            uint32_t l0 = bf2(wv[4*j] - h0x, wv[4*j+1] - h0y);
            uint32_t l1 = bf2(wv[4*j+2] - h1x, wv[4*j+3] - h1y);
            uint32_t d = SWB(o, (ks0 + 4*j) * 2);
            *(uint2*)(sm + XW_BH + d) = make_uint2(h0, h1);
            *(uint2*)(sm + XW_BL + d) = make_uint2(l0, l1);
        }
    }
    __syncthreads();

    int wm = (wid & 1) * 32;
    int wn = (wid >> 1) * 32;
    float acc[2][4][4];
    #pragma unroll
    for (int mt = 0; mt < 2; mt++)
        #pragma unroll
        for (int nt = 0; nt < 4; nt++)
            #pragma unroll
            for (int q = 0; q < 4; q++) acc[mt][nt][q] = 0.f;

    int arow = lane & 15;
    int acolb = (lane >> 4) * 16;
    int brow = lane & 7;
    int bcolb = ((lane >> 3) & 1) * 16;

    #pragma unroll
    for (int ks = 0; ks < 4; ks++) {
        int kb = ks * 32;
        uint32_t ah[2][4], al[2][4];
        #pragma unroll
        for (int mt = 0; mt < 2; mt++) {
            int row = wm + mt * 16 + arow;
            uint32_t ad = SWB(row, kb + acolb);
            ldsm_x4(ah[mt][0], ah[mt][1], ah[mt][2], ah[mt][3], smb + XW_AH + ad);
            ldsm_x4(al[mt][0], al[mt][1], al[mt][2], al[mt][3], smb + XW_AL + ad);
        }
        uint32_t bh[4][2], bl[4][2];
        #pragma unroll
        for (int nt = 0; nt < 4; nt++) {
            int row = wn + nt * 8 + brow;
            uint32_t bd = SWB(row, kb + bcolb);
            ldsm_x2(bh[nt][0], bh[nt][1], smb + XW_BH + bd);
            ldsm_x2(bl[nt][0], bl[nt][1], smb + XW_BL + bd);
        }
        #pragma unroll
        for (int mt = 0; mt < 2; mt++)
            #pragma unroll
            for (int nt = 0; nt < 4; nt++) {
                MMA16816(acc[mt][nt], ah[mt][0], ah[mt][1], ah[mt][2], ah[mt][3],
                         bh[nt][0], bh[nt][1]);
                MMA16816(acc[mt][nt], ah[mt][0], ah[mt][1], ah[mt][2], ah[mt][3],
                         bl[nt][0], bl[nt][1]);
                MMA16816(acc[mt][nt], al[mt][0], al[mt][1], al[mt][2], al[mt][3],
                         bh[nt][0], bh[nt][1]);
            }
    }

    int r0 = lane >> 2, c0 = (lane & 3) * 2;
    #pragma unroll
    for (int mt = 0; mt < 2; mt++) {
        int row = wm + mt * 16 + r0;
        #pragma unroll
        for (int nt = 0; nt < 4; nt++) {
            int o = wn + nt * 8 + c0;
            float* p0 = &g_xw[(size_t)(t0 + row) * GH + o];
            float* p1 = &g_xw[(size_t)(t0 + row + 8) * GH + o];
            p0[0] = acc[mt][nt][0]; p0[1] = acc[mt][nt][1];
            p1[0] = acc[mt][nt][2]; p1[1] = acc[mt][nt][3];
        }
    }
}

// ============================================================
// Stage 4: per-graph dense-A GCN aggregate + pool + MLP head
// ============================================================
struct HeadSmem {
    float xw[NN * GH];
    union { int cnt[NN * NN]; float Af[NN * NN]; } a;
    int   degc[NN];
    float dis[NN];
    float bsm[GH];
    float gsm[GH];
    float zsm[GH / 2];
    float pool[8 * GH];
};

__global__ __launch_bounds__(1024) void gcn_head_kernel(
    const int* __restrict__ edge_index,
    const float* __restrict__ gcn_b,
    const float* __restrict__ w1, const float* __restrict__ b1,
    const float* __restrict__ w2, const float* __restrict__ b2,
    float* __restrict__ out)
{
    extern __shared__ char smem_raw[];
    HeadSmem* S = (HeadSmem*)smem_raw;
    int g = blockIdx.x;
    int tid = threadIdx.x;
    const int* srcA = edge_index + g * EG;
    const int* dstA = edge_index + BB * EG + g * EG;

    const float4* xws = (const float4*)(g_xw + (size_t)g * NN * GH);
    #pragma unroll
    for (int i = 0; i < 3; i++) {
        int e = tid + i * 1024;
        if (e < NN * GH / 4) ((float4*)S->xw)[e] = xws[e];
    }
    for (int i = tid; i < NN * NN; i += 1024) S->a.cnt[i] = 0;
    if (tid < NN) S->degc[tid] = 1;
    if (tid < GH) S->bsm[tid] = gcn_b[tid];
    __syncthreads();

    if (tid < EG) {
        int s = srcA[tid] - g * NN;
        int d = dstA[tid] - g * NN;
        atomicAdd(&S->a.cnt[d * NN + s], 1);
        atomicAdd(&S->degc[d], 1);
    }
    __syncthreads();

    if (tid < NN) S->dis[tid] = rsqrtf((float)S->degc[tid]);
    __syncthreads();

    for (int i = tid; i < NN * NN; i += 1024) {
        int d = i / NN, s = i - d * NN;
        float c = (float)S->a.cnt[i];
        float v = c * S->dis[d] * S->dis[s];
        if (d == s) v += S->dis[d] * S->dis[d];
        S->a.Af[i] = v;
    }
    __syncthreads();

    int ch = tid & 127, oct = tid >> 7;
    float acc[9];
    #pragma unroll
    for (int i = 0; i < 9; i++) acc[i] = 0.f;
    int nacc = (oct < 4) ? 9 : 8;

    for (int s = 0; s < NN; s++) {
        float xv = S->xw[s * GH + ch];
        const float* acol = &S->a.Af[s];
        #pragma unroll
        for (int i = 0; i < 9; i++) {
            int nd = oct + i * 8;
            if (nd < NN)
                acc[i] = fmaf(acol[nd * NN], xv, acc[i]);
        }
    }
    float b = S->bsm[ch];
    float pacc = 0.f;
    #pragma unroll
    for (int i = 0; i < 9; i++)
        if (i < nacc) pacc += fmaxf(acc[i] + b, 0.f);
    S->pool[oct * GH + ch] = pacc;
    __syncthreads();

    if (tid < GH) {
        float s = 0.f;
        #pragma unroll
        for (int i = 0; i < 8; i++) s += S->pool[i * GH + tid];
        S->gsm[tid] = s * (1.0f / (float)NN);
    }
    __syncthreads();

    if (tid < GH / 2) {
        float b0a = b1[tid], b0b = 0.f;
        #pragma unroll
        for (int c = 0; c < GH; c += 2) {
            b0a = fmaf(S->gsm[c],     w1[c * (GH / 2) + tid],       b0a);
            b0b = fmaf(S->gsm[c + 1], w1[(c + 1) * (GH / 2) + tid], b0b);
        }
        S->zsm[tid] = fmaxf(b0a + b0b, 0.f);
    }
    __syncthreads();

    if (tid < OUTD) {
        float accv = b2[tid];
        for (int j = 0; j < GH / 2; j++)
            accv = fmaf(S->zsm[j], w2[j * OUTD + tid], accv);
        out[g * OUTD + tid] = accv;
    }
}

extern "C" void kernel_launch(void* const* d_in, const int* in_sizes, int n_in,
                              void* d_out, int out_size)
{
    const float* x        = (const float*)d_in[0];
    const int*   edge_idx = (const int*)  d_in[1];
    const float* conv_w   = (const float*)d_in[3];
    const float* conv_b   = (const float*)d_in[4];
    const float* lin1_w   = (const float*)d_in[5];
    const float* lin1_b   = (const float*)d_in[6];
    const float* gcn_w    = (const float*)d_in[7];
    const float* gcn_b    = (const float*)d_in[8];
    const float* mlp_w1   = (const float*)d_in[9];
    const float* mlp_b1   = (const float*)d_in[10];
    const float* mlp_w2   = (const float*)d_in[11];
    const float* mlp_b2   = (const float*)d_in[12];
    float* out = (float*)d_out;

    cudaFuncSetAttribute(conv_pool_kernel,
                         cudaFuncAttributeMaxDynamicSharedMemorySize, CV_TOTAL);
    cudaFuncSetAttribute(lin1_mma_kernel,
                         cudaFuncAttributeMaxDynamicSharedMemorySize, L1_TOTAL);
    cudaFuncSetAttribute(gcn_xw_kernel,
                         cudaFuncAttributeMaxDynamicSharedMemorySize, XW_TOTAL);
    cudaFuncSetAttribute(gcn_head_kernel,
                         cudaFuncAttributeMaxDynamicSharedMemorySize,
                         (int)sizeof(HeadSmem));

    conv_pool_kernel<<<TT, 256, CV_TOTAL>>>(x, conv_w, conv_b);
    lin1_mma_kernel<<<dim3(NN, KSPLIT), 256, L1_TOTAL>>>(lin1_w);
    gcn_xw_kernel<<<TT / 64, 256, XW_TOTAL>>>(lin1_b, gcn_w);
    gcn_head_kernel<<<BB, 1024, sizeof(HeadSmem)>>>(
        edge_idx, gcn_b, mlp_w1, mlp_b1, mlp_w2, mlp_b2, out);
}

// round 16
// speedup vs baseline: 1.4283x; 1.4283x over previous
#include <cuda_runtime.h>
#include <cuda_bf16.h>
#include <cstdint>

#define BB 128          // graphs
#define NN 68           // landmarks per graph
#define CC 3            // input channels
#define PP 32           // patch
#define KK 16           // conv kernels
#define FD 64           // feature dim
#define GH 128          // gcn hidden
#define OUTD 2
#define EG (8*NN)       // 544 edges per graph
#define TT (BB*NN)      // 8704 nodes
#define FLAT (KK*(PP/2)*(PP/2))   // 4096
#define KSPLIT 4
#define NCHUNK ((FLAT / KSPLIT) / 64)   // 16

typedef unsigned long long u64;

// ---- scratch (allocation-free: device globals) ----
__device__ float g_flat[(size_t)TT * FLAT];               // fp32 activations
__device__ float g_part[KSPLIT][(size_t)BB * NN * FD];    // k-split partials
__device__ float g_xw[(size_t)TT * GH];
__device__ float g_pool[BB * GH];                         // pooled per-graph vec
__device__ __align__(16) float g_U[NN * KK * CC * 16];    // Winograd weights

// ---- f32x2 helpers ----
__device__ __forceinline__ u64 pk2(float lo, float hi) {
    u64 r; asm("mov.b64 %0, {%1, %2};" : "=l"(r) : "f"(lo), "f"(hi)); return r;
}
__device__ __forceinline__ void upk2(u64 v, float& lo, float& hi) {
    asm("mov.b64 {%0, %1}, %2;" : "=f"(lo), "=f"(hi) : "l"(v));
}
__device__ __forceinline__ u64 fma2(u64 a, u64 b, u64 c) {
    u64 d; asm("fma.rn.f32x2 %0, %1, %2, %3;" : "=l"(d) : "l"(a), "l"(b), "l"(c)); return d;
}
__device__ __forceinline__ u64 mul2(u64 a, u64 b) {
    u64 d; asm("mul.rn.f32x2 %0, %1, %2;" : "=l"(d) : "l"(a), "l"(b)); return d;
}
__device__ __forceinline__ u64 add2(u64 a, u64 b) {
    u64 d; asm("add.rn.f32x2 %0, %1, %2;" : "=l"(d) : "l"(a), "l"(b)); return d;
}
#define NEG2(v) ((v) ^ 0x8000000080000000ULL)

__device__ __forceinline__ uint32_t bf2(float lo, float hi) {
    uint32_t r; asm("cvt.rn.bf16x2.f32 %0, %1, %2;" : "=r"(r) : "f"(hi), "f"(lo)); return r;
}

// ============================================================
// Stage 0: Winograd weight transform U = G g G^T for all (n,k,c)
// ============================================================
__global__ __launch_bounds__(64) void ucompute_kernel(const float* __restrict__ conv_w)
{
    int n = blockIdx.x;
    int tid = threadIdx.x;
    if (tid >= KK * CC) return;
    int k = tid / CC, c = tid % CC;
    const float* gw = conv_w + ((size_t)n * KK + k) * 27 + c * 9;
    float g0 = gw[0], g1 = gw[1], g2 = gw[2];
    float g3 = gw[3], g4 = gw[4], g5 = gw[5];
    float g6 = gw[6], g7 = gw[7], g8 = gw[8];
    float T[4][3];
    T[0][0] = g0;              T[0][1] = g1;              T[0][2] = g2;
    T[1][0] = 0.5f*(g0+g3+g6); T[1][1] = 0.5f*(g1+g4+g7); T[1][2] = 0.5f*(g2+g5+g8);
    T[2][0] = 0.5f*(g0-g3+g6); T[2][1] = 0.5f*(g1-g4+g7); T[2][2] = 0.5f*(g2-g5+g8);
    T[3][0] = g6;              T[3][1] = g7;              T[3][2] = g8;
    float* up = &g_U[((n * KK + k) * CC + c) * 16];
    #pragma unroll
    for (int i = 0; i < 4; i++) {
        float t0 = T[i][0], t1 = T[i][1], t2 = T[i][2];
        up[i*4+0] = t0;
        up[i*4+1] = 0.5f*(t0+t1+t2);
        up[i*4+2] = 0.5f*(t0-t1+t2);
        up[i*4+3] = t2;
    }
}

// ============================================================
// Stage 1: Winograd F(2x2,3x3) conv + bias + relu + maxpool2x2
// (R14 version — f32x2 packed, unroll 2)
// ============================================================
__global__ __launch_bounds__(256) void conv_pool_kernel(
    const float* __restrict__ x,
    const float* __restrict__ conv_b)
{
    int t = blockIdx.x;
    int n = t % NN;
    __shared__ float xs[CC][PP][PP];
    __shared__ __align__(16) float usm[KK][CC][16];
    __shared__ float bsh[KK];

    int tid = threadIdx.x;
    const float4* xp4 = (const float4*)(x + (size_t)t * (CC * PP * PP));
    #pragma unroll
    for (int i = 0; i < 3; i++)
        ((float4*)xs)[tid + i * 256] = xp4[tid + i * 256];
    if (tid < 192)
        ((float4*)usm)[tid] = ((const float4*)&g_U[n * KK * CC * 16])[tid];
    if (tid < KK) bsh[tid] = conv_b[n * KK + tid];
    __syncthreads();

    int pi = tid >> 4, pj = tid & 15;
    int y0 = 2 * pi, x0 = 2 * pj;

    u64 VP[CC][8];
    #pragma unroll
    for (int c = 0; c < CC; c++) {
        float d[4][4];
        #pragma unroll
        for (int dy = 0; dy < 4; dy++) {
            int yy = y0 + dy - 1;
            #pragma unroll
            for (int dx = 0; dx < 4; dx++) {
                int xx = x0 + dx - 1;
                d[dy][dx] = (yy >= 0 && yy < PP && xx >= 0 && xx < PP)
                            ? xs[c][yy][xx] : 0.f;
            }
        }
        float tt[4][4];
        #pragma unroll
        for (int j = 0; j < 4; j++) {
            tt[0][j] = d[0][j] - d[2][j];
            tt[1][j] = d[1][j] + d[2][j];
            tt[2][j] = d[2][j] - d[1][j];
            tt[3][j] = d[1][j] - d[3][j];
        }
        #pragma unroll
        for (int i = 0; i < 4; i++) {
            float v0 = tt[i][0] - tt[i][2];
            float v1 = tt[i][1] + tt[i][2];
            float v2 = tt[i][2] - tt[i][1];
            float v3 = tt[i][1] - tt[i][3];
            VP[c][i*2 + 0] = pk2(v0, v1);
            VP[c][i*2 + 1] = pk2(v2, v3);
        }
    }

    float* outp = &g_flat[(size_t)t * FLAT + tid];
    #pragma unroll 2
    for (int k = 0; k < KK; k++) {
        u64 MP[8];
        {
            const ulonglong2* u0 = (const ulonglong2*)usm[k][0];
            #pragma unroll
            for (int q = 0; q < 4; q++) {
                ulonglong2 uv = u0[q];
                MP[q*2]   = mul2(VP[0][q*2],   uv.x);
                MP[q*2+1] = mul2(VP[0][q*2+1], uv.y);
            }
            #pragma unroll
            for (int c = 1; c < CC; c++) {
                const ulonglong2* uc = (const ulonglong2*)usm[k][c];
                #pragma unroll
                for (int q = 0; q < 4; q++) {
                    ulonglong2 uv = uc[q];
                    MP[q*2]   = fma2(VP[c][q*2],   uv.x, MP[q*2]);
                    MP[q*2+1] = fma2(VP[c][q*2+1], uv.y, MP[q*2+1]);
                }
            }
        }
        u64 p0a = add2(add2(MP[0], MP[2]), MP[4]);
        u64 p0b = add2(add2(MP[1], MP[3]), MP[5]);
        u64 t0  = add2(MP[4], MP[6]);
        u64 t1  = add2(MP[5], MP[7]);
        u64 p1a = add2(MP[2], NEG2(t0));
        u64 p1b = add2(MP[3], NEG2(t1));
        float q0, q1, q2, q3, r0, r1, r2, r3;
        upk2(p0a, q0, q1); upk2(p0b, q2, q3);
        upk2(p1a, r0, r1); upk2(p1b, r2, r3);
        float y00 = q0 + q1 + q2;
        float y01 = q1 - q2 - q3;
        float y10 = r0 + r1 + r2;
        float y11 = r1 - r2 - r3;
        float m = fmaxf(fmaxf(y00, y01), fmaxf(y10, y11));
        outp[k * 256] = fmaxf(m + bsh[k], 0.f);
    }
}

// ============================================================
// Shared MMA helpers
// ============================================================
#define SWB(row, byteoff) (((row) * 128) + ((byteoff) ^ (((row) & 7) << 4)))

__device__ __forceinline__ uint32_t smem_u32(const void* p) {
    uint32_t a;
    asm("{ .reg .u64 t; cvta.to.shared.u64 t, %1; cvt.u32.u64 %0, t; }" : "=r"(a) : "l"(p));
    return a;
}
__device__ __forceinline__ void ldsm_x4(uint32_t& r0, uint32_t& r1, uint32_t& r2, uint32_t& r3, uint32_t a) {
    asm volatile("ldmatrix.sync.aligned.m8n8.x4.shared.b16 {%0,%1,%2,%3}, [%4];"
                 : "=r"(r0), "=r"(r1), "=r"(r2), "=r"(r3) : "r"(a));
}
__device__ __forceinline__ void ldsm_x2(uint32_t& r0, uint32_t& r1, uint32_t a) {
    asm volatile("ldmatrix.sync.aligned.m8n8.x2.shared.b16 {%0,%1}, [%2];"
                 : "=r"(r0), "=r"(r1) : "r"(a));
}
#define MMA16816(c, a0, a1, a2, a3, b0, b1) \
    asm volatile("mma.sync.aligned.m16n8k16.row.col.f32.bf16.bf16.f32 " \
        "{%0,%1,%2,%3}, {%4,%5,%6,%7}, {%8,%9}, {%0,%1,%2,%3};" \
        : "+f"((c)[0]), "+f"((c)[1]), "+f"((c)[2]), "+f"((c)[3]) \
        : "r"(a0), "r"(a1), "r"(a2), "r"(a3), "r"(b0), "r"(b1))

// ============================================================
// Stage 2: lin1 via mma.sync bf16 + ldmatrix (3-pass split)
// with register-prefetch software pipeline over K chunks
// ============================================================
#define L1_AH 0
#define L1_AL 16384
#define L1_BH 32768
#define L1_BL 40960
#define L1_TOTAL 49152

__global__ __launch_bounds__(256) void lin1_mma_kernel(const float* __restrict__ lin1_w)
{
    extern __shared__ char sm[];
    uint32_t smb = smem_u32(sm);

    int n  = blockIdx.x;
    int kh = blockIdx.y;
    int fbase = kh * (FLAT / KSPLIT);

    int tid  = threadIdx.x;
    int wid  = tid >> 5;
    int lane = tid & 31;
    int wm   = (wid & 3) * 32;
    int wn   = (wid >> 2) * 32;

    float acc[2][4][4];
    #pragma unroll
    for (int mt = 0; mt < 2; mt++)
        #pragma unroll
        for (int nt = 0; nt < 4; nt++)
            #pragma unroll
            for (int q = 0; q < 4; q++) acc[mt][nt][q] = 0.f;

    int arow = lane & 15;
    int acolb = (lane >> 4) * 16;
    int brow = lane & 7;
    int bcolb = ((lane >> 3) & 1) * 16;

    int bo = tid & 63;
    int bfs = (tid >> 6) * 16;

    float4 pa[8];
    float  pb[16];

    {
        int fc = fbase;
        #pragma unroll
        for (int j = 0; j < 8; j++) {
            int e = tid + j * 256;
            int row = e >> 4, q = e & 15;
            pa[j] = ((const float4*)g_flat)[(((size_t)(row * NN + n) * FLAT + fc) >> 2) + q];
        }
        const float* wsrc = lin1_w + ((size_t)n * FLAT + fc + bfs) * FD + bo;
        #pragma unroll
        for (int i = 0; i < 16; i++) pb[i] = wsrc[i * FD];
    }

    #pragma unroll 1
    for (int ci = 0; ci < NCHUNK; ci++) {
        __syncthreads();
        #pragma unroll
        for (int j = 0; j < 8; j++) {
            int e = tid + j * 256;
            int row = e >> 4, q = e & 15;
            float4 v = pa[j];
            uint32_t h0 = bf2(v.x, v.y), h1 = bf2(v.z, v.w);
            float hx = __bfloat162float(__ushort_as_bfloat16((unsigned short)(h0 & 0xFFFF)));
            float hy = __bfloat162float(__ushort_as_bfloat16((unsigned short)(h0 >> 16)));
            float hz = __bfloat162float(__ushort_as_bfloat16((unsigned short)(h1 & 0xFFFF)));
            float hw = __bfloat162float(__ushort_as_bfloat16((unsigned short)(h1 >> 16)));
            uint32_t l0 = bf2(v.x - hx, v.y - hy), l1 = bf2(v.z - hz, v.w - hw);
            uint32_t d = SWB(row, q * 8);
            *(uint2*)(sm + L1_AH + d) = make_uint2(h0, h1);
            *(uint2*)(sm + L1_AL + d) = make_uint2(l0, l1);
        }
        #pragma unroll
        for (int j = 0; j < 4; j++) {
            uint32_t h0 = bf2(pb[4*j], pb[4*j+1]);
            uint32_t h1 = bf2(pb[4*j+2], pb[4*j+3]);
            float h0x = __bfloat162float(__ushort_as_bfloat16((unsigned short)(h0 & 0xFFFF)));
            float h0y = __bfloat162float(__ushort_as_bfloat16((unsigned short)(h0 >> 16)));
            float h1x = __bfloat162float(__ushort_as_bfloat16((unsigned short)(h1 & 0xFFFF)));
            float h1y = __bfloat162float(__ushort_as_bfloat16((unsigned short)(h1 >> 16)));
            uint32_t l0 = bf2(pb[4*j] - h0x, pb[4*j+1] - h0y);
            uint32_t l1 = bf2(pb[4*j+2] - h1x, pb[4*j+3] - h1y);
            uint32_t d = SWB(bo, (bfs + 4*j) * 2);
            *(uint2*)(sm + L1_BH + d) = make_uint2(h0, h1);
            *(uint2*)(sm + L1_BL + d) = make_uint2(l0, l1);
        }
        if (ci + 1 < NCHUNK) {
            int fc = fbase + (ci + 1) * 64;
            #pragma unroll
            for (int j = 0; j < 8; j++) {
                int e = tid + j * 256;
                int row = e >> 4, q = e & 15;
                pa[j] = ((const float4*)g_flat)[(((size_t)(row * NN + n) * FLAT + fc) >> 2) + q];
            }
            const float* wsrc = lin1_w + ((size_t)n * FLAT + fc + bfs) * FD + bo;
            #pragma unroll
            for (int i = 0; i < 16; i++) pb[i] = wsrc[i * FD];
        }
        __syncthreads();

        #pragma unroll
        for (int ks = 0; ks < 4; ks++) {
            int kb = ks * 32;
            uint32_t ah[2][4], al[2][4];
            #pragma unroll
            for (int mt = 0; mt < 2; mt++) {
                int row = wm + mt * 16 + arow;
                uint32_t ad = SWB(row, kb + acolb);
                ldsm_x4(ah[mt][0], ah[mt][1], ah[mt][2], ah[mt][3], smb + L1_AH + ad);
                ldsm_x4(al[mt][0], al[mt][1], al[mt][2], al[mt][3], smb + L1_AL + ad);
            }
            uint32_t bh[4][2], bl[4][2];
            #pragma unroll
            for (int nt = 0; nt < 4; nt++) {
                int row = wn + nt * 8 + brow;
                uint32_t bd = SWB(row, kb + bcolb);
                ldsm_x2(bh[nt][0], bh[nt][1], smb + L1_BH + bd);
                ldsm_x2(bl[nt][0], bl[nt][1], smb + L1_BL + bd);
            }
            #pragma unroll
            for (int mt = 0; mt < 2; mt++)
                #pragma unroll
                for (int nt = 0; nt < 4; nt++) {
                    MMA16816(acc[mt][nt], ah[mt][0], ah[mt][1], ah[mt][2], ah[mt][3],
                             bh[nt][0], bh[nt][1]);
                    MMA16816(acc[mt][nt], ah[mt][0], ah[mt][1], ah[mt][2], ah[mt][3],
                             bl[nt][0], bl[nt][1]);
                    MMA16816(acc[mt][nt], al[mt][0], al[mt][1], al[mt][2], al[mt][3],
                             bh[nt][0], bh[nt][1]);
                }
        }
    }

    float* P = g_part[kh];
    int r0 = lane >> 2, c0 = (lane & 3) * 2;
    #pragma unroll
    for (int mt = 0; mt < 2; mt++) {
        int g0 = wm + mt * 16 + r0;
        #pragma unroll
        for (int nt = 0; nt < 4; nt++) {
            int o = wn + nt * 8 + c0;
            float* p0 = &P[(size_t)(g0 * NN + n) * FD + o];
            float* p1 = &P[(size_t)((g0 + 8) * NN + n) * FD + o];
            p0[0] = acc[mt][nt][0]; p0[1] = acc[mt][nt][1];
            p1[0] = acc[mt][nt][2]; p1[1] = acc[mt][nt][3];
        }
    }
}

// ============================================================
// Stage 3: xw = relu(sum parts + bias) @ gcn_w, via MMA.
// ============================================================
#define XW_AH 0
#define XW_AL 8192
#define XW_BH 16384
#define XW_BL 32768
#define XW_TOTAL 49152

__global__ __launch_bounds__(256) void gcn_xw_kernel(
    const float* __restrict__ lin1_b, const float* __restrict__ gcn_w)
{
    extern __shared__ char sm[];
    uint32_t smb = smem_u32(sm);
    int t0 = blockIdx.x * 64;
    int tid = threadIdx.x;
    int wid = tid >> 5;
    int lane = tid & 31;

    #pragma unroll
    for (int j = 0; j < 4; j++) {
        int e = tid + j * 256;
        int row = e >> 4, q = e & 15;
        int t = t0 + row, n = t % NN;
        size_t ix4 = (size_t)t * 16 + q;
        float sx = 0.f, sy = 0.f, sz = 0.f, sw = 0.f;
        #pragma unroll
        for (int p = 0; p < KSPLIT; p++) {
            float4 pv = ((const float4*)g_part[p])[ix4];
            sx += pv.x; sy += pv.y; sz += pv.z; sw += pv.w;
        }
        float4 lb = ((const float4*)lin1_b)[n * 16 + q];
        float vx = fmaxf(sx + lb.x, 0.f);
        float vy = fmaxf(sy + lb.y, 0.f);
        float vz = fmaxf(sz + lb.z, 0.f);
        float vw = fmaxf(sw + lb.w, 0.f);
        uint32_t h0 = bf2(vx, vy), h1 = bf2(vz, vw);
        float hx = __bfloat162float(__ushort_as_bfloat16((unsigned short)(h0 & 0xFFFF)));
        float hy = __bfloat162float(__ushort_as_bfloat16((unsigned short)(h0 >> 16)));
        float hz = __bfloat162float(__ushort_as_bfloat16((unsigned short)(h1 & 0xFFFF)));
        float hw = __bfloat162float(__ushort_as_bfloat16((unsigned short)(h1 >> 16)));
        uint32_t l0 = bf2(vx - hx, vy - hy), l1 = bf2(vz - hz, vw - hw);
        uint32_t d = SWB(row, q * 8);
        *(uint2*)(sm + XW_AH + d) = make_uint2(h0, h1);
        *(uint2*)(sm + XW_AL + d) = make_uint2(l0, l1);
    }
    {
        int o = tid & 127;
        int ks0 = (tid >> 7) * 32;
        float wv[32];
        #pragma unroll
        for (int i = 0; i < 32; i++) wv[i] = gcn_w[(ks0 + i) * GH + o];
        #pragma unroll
        for (int j = 0; j < 8; j++) {
            uint32_t h0 = bf2(wv[4*j], wv[4*j+1]);
            uint32_t h1 = bf2(wv[4*j+2], wv[4*j+3]);
            float h0x = __bfloat162float(__ushort_as_bfloat16((unsigned short)(h0 & 0xFFFF)));
            float h0y = __bfloat162float(__ushort_as_bfloat16((unsigned short)(h0 >> 16)));
            float h1x = __bfloat162float(__ushort_as_bfloat16((unsigned short)(h1 & 0xFFFF)));
            float h1y = __bfloat162float(__ushort_as_bfloat16((unsigned short)(h1 >> 16)));
            uint32_t l0 = bf2(wv[4*j] - h0x, wv[4*j+1] - h0y);
            uint32_t l1 = bf2(wv[4*j+2] - h1x, wv[4*j+3] - h1y);
            uint32_t d = SWB(o, (ks0 + 4*j) * 2);
            *(uint2*)(sm + XW_BH + d) = make_uint2(h0, h1);
            *(uint2*)(sm + XW_BL + d) = make_uint2(l0, l1);
        }
    }
    __syncthreads();

    int wm = (wid & 1) * 32;
    int wn = (wid >> 1) * 32;
    float acc[2][4][4];
    #pragma unroll
    for (int mt = 0; mt < 2; mt++)
        #pragma unroll
        for (int nt = 0; nt < 4; nt++)
            #pragma unroll
            for (int q = 0; q < 4; q++) acc[mt][nt][q] = 0.f;

    int arow = lane & 15;
    int acolb = (lane >> 4) * 16;
    int brow = lane & 7;
    int bcolb = ((lane >> 3) & 1) * 16;

    #pragma unroll
    for (int ks = 0; ks < 4; ks++) {
        int kb = ks * 32;
        uint32_t ah[2][4], al[2][4];
        #pragma unroll
        for (int mt = 0; mt < 2; mt++) {
            int row = wm + mt * 16 + arow;
            uint32_t ad = SWB(row, kb + acolb);
            ldsm_x4(ah[mt][0], ah[mt][1], ah[mt][2], ah[mt][3], smb + XW_AH + ad);
            ldsm_x4(al[mt][0], al[mt][1], al[mt][2], al[mt][3], smb + XW_AL + ad);
        }
        uint32_t bh[4][2], bl[4][2];
        #pragma unroll
        for (int nt = 0; nt < 4; nt++) {
            int row = wn + nt * 8 + brow;
            uint32_t bd = SWB(row, kb + bcolb);
            ldsm_x2(bh[nt][0], bh[nt][1], smb + XW_BH + bd);
            ldsm_x2(bl[nt][0], bl[nt][1], smb + XW_BL + bd);
        }
        #pragma unroll
        for (int mt = 0; mt < 2; mt++)
            #pragma unroll
            for (int nt = 0; nt < 4; nt++) {
                MMA16816(acc[mt][nt], ah[mt][0], ah[mt][1], ah[mt][2], ah[mt][3],
                         bh[nt][0], bh[nt][1]);
                MMA16816(acc[mt][nt], ah[mt][0], ah[mt][1], ah[mt][2], ah[mt][3],
                         bl[nt][0], bl[nt][1]);
                MMA16816(acc[mt][nt], al[mt][0], al[mt][1], al[mt][2], al[mt][3],
                         bh[nt][0], bh[nt][1]);
            }
    }

    int r0 = lane >> 2, c0 = (lane & 3) * 2;
    #pragma unroll
    for (int mt = 0; mt < 2; mt++) {
        int row = wm + mt * 16 + r0;
        #pragma unroll
        for (int nt = 0; nt < 4; nt++) {
            int o = wn + nt * 8 + c0;
            float* p0 = &g_xw[(size_t)(t0 + row) * GH + o];
            float* p1 = &g_xw[(size_t)(t0 + row + 8) * GH + o];
            p0[0] = acc[mt][nt][0]; p0[1] = acc[mt][nt][1];
            p1[0] = acc[mt][nt][2]; p1[1] = acc[mt][nt][3];
        }
    }
}

// ============================================================
// Stage 4: per-graph dense-A GCN aggregate + mean-pool,
// split 2x by channel-half. grid (BB, 2), 1024 threads.
// Writes pooled half-vector to g_pool.
// ============================================================
struct HeadSmem {
    float xw[NN * 64];                   // this half's channels
    union { int cnt[NN * NN]; float Af[NN * NN]; } a;
    int   degc[NN];
    float dis[NN];
    float bsm[64];
    float pool[16 * 64];
};

__global__ __launch_bounds__(1024) void gcn_head_kernel(
    const int* __restrict__ edge_index,
    const float* __restrict__ gcn_b)
{
    extern __shared__ char smem_raw[];
    HeadSmem* S = (HeadSmem*)smem_raw;
    int g = blockIdx.x;
    int half = blockIdx.y;
    int ch0 = half * 64;
    int tid = threadIdx.x;
    const int* srcA = edge_index + g * EG;
    const int* dstA = edge_index + BB * EG + g * EG;

    // load this half's xw columns: 68 rows x 64 ch = 1088 float4
    #pragma unroll
    for (int i = 0; i < 2; i++) {
        int e = tid + i * 1024;
        if (e < NN * 16) {
            int row = e >> 4, q = e & 15;
            ((float4*)S->xw)[e] =
                *(const float4*)(g_xw + (size_t)(g * NN + row) * GH + ch0 + q * 4);
        }
    }
    for (int i = tid; i < NN * NN; i += 1024) S->a.cnt[i] = 0;
    if (tid < NN) S->degc[tid] = 1;
    if (tid < 64) S->bsm[tid] = gcn_b[ch0 + tid];
    __syncthreads();

    if (tid < EG) {
        int s = srcA[tid] - g * NN;
        int d = dstA[tid] - g * NN;
        atomicAdd(&S->a.cnt[d * NN + s], 1);
        atomicAdd(&S->degc[d], 1);
    }
    __syncthreads();

    if (tid < NN) S->dis[tid] = rsqrtf((float)S->degc[tid]);
    __syncthreads();

    for (int i = tid; i < NN * NN; i += 1024) {
        int d = i / NN, s = i - d * NN;
        float c = (float)S->a.cnt[i];
        float v = c * S->dis[d] * S->dis[s];
        if (d == s) v += S->dis[d] * S->dis[d];
        S->a.Af[i] = v;
    }
    __syncthreads();

    // dense aggregate: ch = tid&63, group = tid>>6 (16 groups of nodes)
    int ch = tid & 63, grp = tid >> 6;
    float acc[5];
    #pragma unroll
    for (int i = 0; i < 5; i++) acc[i] = 0.f;
    int nacc = (grp < 4) ? 5 : 4;        // nd = grp + i*16 < 68

    for (int s = 0; s < NN; s++) {
        float xv = S->xw[s * 64 + ch];
        const float* acol = &S->a.Af[s];
        #pragma unroll
        for (int i = 0; i < 5; i++) {
            int nd = grp + i * 16;
            if (nd < NN)
                acc[i] = fmaf(acol[nd * NN], xv, acc[i]);
        }
    }
    float b = S->bsm[ch];
    float pacc = 0.f;
    #pragma unroll
    for (int i = 0; i < 5; i++)
        if (i < nacc) pacc += fmaxf(acc[i] + b, 0.f);
    S->pool[grp * 64 + ch] = pacc;
    __syncthreads();

    if (tid < 64) {
        float s = 0.f;
        #pragma unroll
        for (int i = 0; i < 16; i++) s += S->pool[i * 64 + tid];
        g_pool[g * GH + ch0 + tid] = s * (1.0f / (float)NN);
    }
}

// ============================================================
// Stage 5: MLP head (tiny): z = relu(g@w1+b1); out = z@w2+b2
// ============================================================
__global__ __launch_bounds__(128) void head2_kernel(
    const float* __restrict__ w1, const float* __restrict__ b1,
    const float* __restrict__ w2, const float* __restrict__ b2,
    float* __restrict__ out)
{
    int g = blockIdx.x;
    int tid = threadIdx.x;
    __shared__ float gsm[GH];
    __shared__ float zsm[GH / 2];

    gsm[tid] = g_pool[g * GH + tid];
    __syncthreads();

    if (tid < GH / 2) {
        float a0 = b1[tid], a1 = 0.f;
        #pragma unroll
        for (int c = 0; c < GH; c += 2) {
            a0 = fmaf(gsm[c],     w1[c * (GH / 2) + tid],       a0);
            a1 = fmaf(gsm[c + 1], w1[(c + 1) * (GH / 2) + tid], a1);
        }
        zsm[tid] = fmaxf(a0 + a1, 0.f);
    }
    __syncthreads();

    if (tid < OUTD) {
        float accv = b2[tid];
        for (int j = 0; j < GH / 2; j++)
            accv = fmaf(zsm[j], w2[j * OUTD + tid], accv);
        out[g * OUTD + tid] = accv;
    }
}

extern "C" void kernel_launch(void* const* d_in, const int* in_sizes, int n_in,
                              void* d_out, int out_size)
{
    const float* x        = (const float*)d_in[0];
    const int*   edge_idx = (const int*)  d_in[1];
    const float* conv_w   = (const float*)d_in[3];
    const float* conv_b   = (const float*)d_in[4];
    const float* lin1_w   = (const float*)d_in[5];
    const float* lin1_b   = (const float*)d_in[6];
    const float* gcn_w    = (const float*)d_in[7];
    const float* gcn_b    = (const float*)d_in[8];
    const float* mlp_w1   = (const float*)d_in[9];
    const float* mlp_b1   = (const float*)d_in[10];
    const float* mlp_w2   = (const float*)d_in[11];
    const float* mlp_b2   = (const float*)d_in[12];
    float* out = (float*)d_out;

    cudaFuncSetAttribute(lin1_mma_kernel,
                         cudaFuncAttributeMaxDynamicSharedMemorySize, L1_TOTAL);
    cudaFuncSetAttribute(gcn_xw_kernel,
                         cudaFuncAttributeMaxDynamicSharedMemorySize, XW_TOTAL);
    cudaFuncSetAttribute(gcn_head_kernel,
                         cudaFuncAttributeMaxDynamicSharedMemorySize,
                         (int)sizeof(HeadSmem));

    ucompute_kernel<<<NN, 64>>>(conv_w);
    conv_pool_kernel<<<TT, 256>>>(x, conv_b);
    lin1_mma_kernel<<<dim3(NN, KSPLIT), 256, L1_TOTAL>>>(lin1_w);
    gcn_xw_kernel<<<TT / 64, 256, XW_TOTAL>>>(lin1_b, gcn_w);
    gcn_head_kernel<<<dim3(BB, 2), 1024, sizeof(HeadSmem)>>>(edge_idx, gcn_b);
    head2_kernel<<<BB, 128>>>(mlp_w1, mlp_b1, mlp_w2, mlp_b2, out);
}